// round 1
// baseline (speedup 1.0000x reference)
#include <cuda_runtime.h>
#include <cuda_bf16.h>
#include <cstddef>

#define N_  16
#define K_  256
#define T_  1000
#define M_  384
#define P_  2
#define C8  8

// ---------------- scratch (device globals; no allocations) ----------------
__device__ float g_g [N_ * K_ * 16];   // folded layer-1 bias per (n,k)
__device__ float g_ga[N_ * K_ * 2];    // folded aux layer-1 bias per (n,k)
__device__ float g_W [N_ * T_ * K_];   // softmax weights
__device__ float g_wc[N_ * T_ * 2];    // sum_k W*C  (before proj)

__device__ __forceinline__ float sigmoidf_fast(float x) {
    return __fdividef(1.0f, 1.0f + __expf(-x));
}
__device__ __forceinline__ float siluf(float x) {
    return x * sigmoidf_fast(x);
}

// ---------------------------------------------------------------------------
// Kernel 1: durations + exclusive cumsum + Conv1D(3, same)+BN+silu over K,
// then fold everything into g[n,k,16] and ga[n,k,2].
// Grid: N_ blocks, K_ threads (thread = k).
// ---------------------------------------------------------------------------
__global__ void prep_kernel(
    const float* __restrict__ V,          // [N,K,M]
    const float* __restrict__ dur_out,    // [N,K]
    const float* __restrict__ conv_w,     // [3,M,8]
    const float* __restrict__ conv_b,     // [8]
    const float* __restrict__ bn_gamma, const float* __restrict__ bn_beta,
    const float* __restrict__ bn_mean,  const float* __restrict__ bn_var,
    const float* __restrict__ w1,         // [10,16]
    const float* __restrict__ b1,         // [16]
    const float* __restrict__ aw1,        // [10,2]
    const float* __restrict__ ab1)        // [2]
{
    __shared__ float s_cw[3 * M_ * C8];   // 36 KB
    __shared__ float s_scan[K_];

    const int n = blockIdx.x;
    const int k = threadIdx.x;

    // stage conv weights in shared (broadcast reads later)
    for (int i = k; i < 3 * M_ * C8; i += K_) s_cw[i] = conv_w[i];

    // durations + inclusive scan (Hillis-Steele)
    const float duration = fmaxf(__expf(dur_out[n * K_ + k]) - 1.0f, 0.0f);
    s_scan[k] = duration;
    __syncthreads();
    for (int off = 1; off < K_; off <<= 1) {
        float add = (k >= off) ? s_scan[k - off] : 0.0f;
        __syncthreads();
        s_scan[k] += add;
        __syncthreads();
    }
    const float Ev = s_scan[k];          // inclusive cumsum = E
    const float Sv = Ev - duration;      // exclusive cumsum = S

    // Conv1D over K dim (kernel 3, SAME zero padding), 8 output channels
    float acc[C8];
#pragma unroll
    for (int o = 0; o < C8; o++) acc[o] = 0.0f;
    for (int tap = 0; tap < 3; tap++) {
        int kk = k - 1 + tap;
        if (kk < 0 || kk >= K_) continue;
        const float* vrow = V + ((size_t)n * K_ + kk) * M_;
        const float* wtap = s_cw + tap * M_ * C8;
        for (int c = 0; c < M_; c++) {
            float v = vrow[c];
            const float* wr = wtap + c * C8;
#pragma unroll
            for (int o = 0; o < C8; o++) acc[o] = fmaf(v, wr[o], acc[o]);
        }
    }

    // BN (inference, eps=1e-3) + silu
    float cv[C8];
#pragma unroll
    for (int o = 0; o < C8; o++) {
        float y = (acc[o] + conv_b[o] - bn_mean[o]) * rsqrtf(bn_var[o] + 1e-3f)
                  * bn_gamma[o] + bn_beta[o];
        cv[o] = siluf(y);
    }

    // Fold into g: b1 - S*w1[0] + E*w1[1] + cv @ w1[2:10]
    float* gout = g_g + ((size_t)n * K_ + k) * 16;
#pragma unroll
    for (int j = 0; j < 16; j++) {
        float gj = b1[j] - Sv * w1[j] + Ev * w1[16 + j];
#pragma unroll
        for (int c = 0; c < C8; c++) gj = fmaf(cv[c], w1[(2 + c) * 16 + j], gj);
        gout[j] = gj;
    }
    float* gaout = g_ga + ((size_t)n * K_ + k) * 2;
#pragma unroll
    for (int p = 0; p < P_; p++) {
        float gp = ab1[p] - Sv * aw1[p] + Ev * aw1[2 + p];
#pragma unroll
        for (int c = 0; c < C8; c++) gp = fmaf(cv[c], aw1[(2 + c) * 2 + p], gp);
        gaout[p] = gp;
    }
}

// ---------------------------------------------------------------------------
// Kernel 2: per (n,t): score MLP -> softmax over K -> W; aux MLP -> wc.
// Grid: (T_, N_), block K_ threads (thread = k).
// ---------------------------------------------------------------------------
__global__ void score_kernel(
    const float* __restrict__ w1,   // [10,16] (for d1)
    const float* __restrict__ w2,   // [16,16]
    const float* __restrict__ b2,   // [16]
    const float* __restrict__ w3,   // [16,1]
    const float* __restrict__ b3,   // [1]
    const float* __restrict__ aw1,  // [10,2] (for da)
    const float* __restrict__ aw2,  // [2,2]
    const float* __restrict__ ab2)  // [2]
{
    __shared__ float s_w2[256];
    __shared__ float s_d1[16], s_w3[16], s_b2[16];
    __shared__ float s_da[2], s_aw2[4], s_ab2[2], s_b3;
    __shared__ float red0[K_], red1[K_], red2[K_];

    const int tix = blockIdx.x;          // 0..T-1
    const int n   = blockIdx.y;
    const int k   = threadIdx.x;
    const float t = (float)(tix + 1);

    if (k < 256) s_w2[k] = w2[k];
    if (k < 16) { s_d1[k] = w1[k] - w1[16 + k]; s_w3[k] = w3[k]; s_b2[k] = b2[k]; }
    if (k < 2)  { s_da[k] = aw1[k] - aw1[2 + k]; s_ab2[k] = ab2[k]; }
    if (k < 4)  { s_aw2[k] = aw2[k]; }
    if (k == 0) { s_b3 = b3[0]; }
    __syncthreads();

    // layer 1 (folded)
    const float* g = g_g + ((size_t)n * K_ + k) * 16;
    float h1[16];
#pragma unroll
    for (int j = 0; j < 16; j++) {
        float x = fmaf(t, s_d1[j], g[j]);
        h1[j] = siluf(x);
    }
    // layer 2 + output
    float score = s_b3;
#pragma unroll
    for (int i = 0; i < 16; i++) {
        float a = s_b2[i];
#pragma unroll
        for (int j = 0; j < 16; j++) a = fmaf(h1[j], s_w2[j * 16 + i], a);
        score = fmaf(siluf(a), s_w3[i], score);
    }

    // aux MLP (P=2)
    const float* ga = g_ga + ((size_t)n * K_ + k) * 2;
    float a0 = siluf(fmaf(t, s_da[0], ga[0]));
    float a1 = siluf(fmaf(t, s_da[1], ga[1]));
    float c20 = siluf(s_ab2[0] + a0 * s_aw2[0] + a1 * s_aw2[2]);
    float c21 = siluf(s_ab2[1] + a0 * s_aw2[1] + a1 * s_aw2[3]);

    // softmax over K (max then sum)
    red0[k] = score;
    __syncthreads();
    for (int s = K_ / 2; s > 0; s >>= 1) {
        if (k < s) red0[k] = fmaxf(red0[k], red0[k + s]);
        __syncthreads();
    }
    const float mx = red0[0];
    __syncthreads();

    const float e = __expf(score - mx);
    red0[k] = e;
    red1[k] = e * c20;
    red2[k] = e * c21;
    __syncthreads();
    for (int s = K_ / 2; s > 0; s >>= 1) {
        if (k < s) {
            red0[k] += red0[k + s];
            red1[k] += red1[k + s];
            red2[k] += red2[k + s];
        }
        __syncthreads();
    }
    const float inv = __fdividef(1.0f, red0[0]);

    g_W[((size_t)n * T_ + tix) * K_ + k] = e * inv;
    if (k == 0) {
        g_wc[((size_t)n * T_ + tix) * 2 + 0] = red1[0] * inv;
        g_wc[((size_t)n * T_ + tix) * 2 + 1] = red2[0] * inv;
    }
}

// ---------------------------------------------------------------------------
// Kernel 3: O[n,t,m] = sum_k W[n,t,k]*V[n,k,m] + wc[n,t,:] @ proj_w[:,m]
// Tiled fp32 GEMM: 64x64x16, 256 threads, 4x4 register microtile.
// Grid: (M/64, ceil(T/64), N)
// ---------------------------------------------------------------------------
#define BT 64
#define BM 64
#define BK 16

__global__ void out_gemm_kernel(
    const float* __restrict__ V,       // [N,K,M]
    const float* __restrict__ proj_w,  // [2,M]
    float* __restrict__ O)             // [N,T,M]
{
    __shared__ float As[BK][BT + 1];   // +1 pad: conflict-free k-major stores
    __shared__ float Bs[BK][BM];

    const int n  = blockIdx.z;
    const int t0 = blockIdx.y * BT;
    const int m0 = blockIdx.x * BM;

    const int tid = threadIdx.x;       // 256
    const int tx  = tid & 15;
    const int ty  = tid >> 4;

    const float* A = g_W + (size_t)n * T_ * K_;   // [T,K]
    const float* B = V   + (size_t)n * K_ * M_;   // [K,M]

    float acc[4][4];
#pragma unroll
    for (int i = 0; i < 4; i++)
#pragma unroll
        for (int j = 0; j < 4; j++) acc[i][j] = 0.0f;

    for (int k0 = 0; k0 < K_; k0 += BK) {
#pragma unroll
        for (int i = tid; i < BT * BK; i += 256) {
            // A: k fast-varying across threads (coalesced-ish 64B runs)
            int akk = i & 15, att = i >> 4;
            int tg = t0 + att;
            As[akk][att] = (tg < T_) ? A[(size_t)tg * K_ + k0 + akk] : 0.0f;
            // B: m fast-varying (fully coalesced)
            int bkk = i >> 6, bmm = i & 63;
            Bs[bkk][bmm] = B[(size_t)(k0 + bkk) * M_ + m0 + bmm];
        }
        __syncthreads();

#pragma unroll
        for (int kk = 0; kk < BK; kk++) {
            float ra[4];
            float4 rb4 = *reinterpret_cast<const float4*>(&Bs[kk][tx * 4]);
            float rb[4] = { rb4.x, rb4.y, rb4.z, rb4.w };
#pragma unroll
            for (int i = 0; i < 4; i++) ra[i] = As[kk][ty * 4 + i];
#pragma unroll
            for (int i = 0; i < 4; i++)
#pragma unroll
                for (int j = 0; j < 4; j++)
                    acc[i][j] = fmaf(ra[i], rb[j], acc[i][j]);
        }
        __syncthreads();
    }

    // epilogue: += wc @ proj_w, store
    const int m = m0 + tx * 4;
#pragma unroll
    for (int i = 0; i < 4; i++) {
        int tg = t0 + ty * 4 + i;
        if (tg >= T_) continue;
        float wc0 = g_wc[((size_t)n * T_ + tg) * 2 + 0];
        float wc1 = g_wc[((size_t)n * T_ + tg) * 2 + 1];
        float4 out;
        out.x = acc[i][0] + wc0 * proj_w[m + 0] + wc1 * proj_w[M_ + m + 0];
        out.y = acc[i][1] + wc0 * proj_w[m + 1] + wc1 * proj_w[M_ + m + 1];
        out.z = acc[i][2] + wc0 * proj_w[m + 2] + wc1 * proj_w[M_ + m + 2];
        out.w = acc[i][3] + wc0 * proj_w[m + 3] + wc1 * proj_w[M_ + m + 3];
        *reinterpret_cast<float4*>(&O[(((size_t)n * T_ + tg) * M_) + m]) = out;
    }
}

// ---------------------------------------------------------------------------
extern "C" void kernel_launch(void* const* d_in, const int* in_sizes, int n_in,
                              void* d_out, int out_size)
{
    const float* V        = (const float*)d_in[0];
    const float* dur      = (const float*)d_in[1];
    const float* conv_w   = (const float*)d_in[2];
    const float* conv_b   = (const float*)d_in[3];
    const float* bn_gamma = (const float*)d_in[4];
    const float* bn_beta  = (const float*)d_in[5];
    const float* bn_mean  = (const float*)d_in[6];
    const float* bn_var   = (const float*)d_in[7];
    const float* w1       = (const float*)d_in[8];
    const float* b1       = (const float*)d_in[9];
    const float* w2       = (const float*)d_in[10];
    const float* b2       = (const float*)d_in[11];
    const float* w3       = (const float*)d_in[12];
    const float* b3       = (const float*)d_in[13];
    const float* aw1      = (const float*)d_in[14];
    const float* ab1      = (const float*)d_in[15];
    const float* aw2      = (const float*)d_in[16];
    const float* ab2      = (const float*)d_in[17];
    const float* proj_w   = (const float*)d_in[18];
    float* O = (float*)d_out;

    prep_kernel<<<N_, K_>>>(V, dur, conv_w, conv_b, bn_gamma, bn_beta,
                            bn_mean, bn_var, w1, b1, aw1, ab1);
    score_kernel<<<dim3(T_, N_), K_>>>(w1, w2, b2, w3, b3, aw1, aw2, ab2);
    out_gemm_kernel<<<dim3(M_ / BM, (T_ + BT - 1) / BT, N_), 256>>>(V, proj_w, O);
}

// round 2
// speedup vs baseline: 2.0150x; 2.0150x over previous
#include <cuda_runtime.h>
#include <cuda_bf16.h>
#include <cstddef>

#define N_  16
#define K_  256
#define T_  1000
#define M_  384
#define P_  2
#define C8  8
#define TT  8      // t-rows per score block

typedef unsigned long long u64;

// ---------------- scratch (device globals; no allocations) ----------------
__device__ float g_SE[N_ * K_ * 2];    // S, E per (n,k)
__device__ float g_g [N_ * K_ * 16];   // folded layer-1 bias per (n,k)
__device__ float g_ga[N_ * K_ * 2];    // folded aux layer-1 bias per (n,k)
__device__ float g_W [N_ * T_ * K_];   // softmax weights
__device__ float g_wc[N_ * T_ * 2];    // sum_k W*C  (before proj)

// ---------------- packed fp32x2 helpers (sm_100 FFMA2 path) ---------------
__device__ __forceinline__ u64 pk2(float lo, float hi) {
    u64 d; asm("mov.b64 %0, {%1, %2};" : "=l"(d) : "f"(lo), "f"(hi)); return d;
}
__device__ __forceinline__ u64 pkd(float x) {
    u64 d; asm("mov.b64 %0, {%1, %1};" : "=l"(d) : "f"(x)); return d;
}
__device__ __forceinline__ void upk(u64 v, float& lo, float& hi) {
    asm("mov.b64 {%0, %1}, %2;" : "=f"(lo), "=f"(hi) : "l"(v));
}
__device__ __forceinline__ u64 ffma2(u64 a, u64 b, u64 c) {
    u64 d; asm("fma.rn.f32x2 %0, %1, %2, %3;" : "=l"(d) : "l"(a), "l"(b), "l"(c));
    return d;
}

__device__ __forceinline__ float siluf(float x) {
    return x * __fdividef(1.0f, 1.0f + __expf(-x));
}

// ---------------------------------------------------------------------------
// Kernel 0: durations + scan -> S,E.  Grid N_, block K_.
// ---------------------------------------------------------------------------
__global__ void scan_kernel(const float* __restrict__ dur_out)
{
    __shared__ float wsum[8];
    const int n = blockIdx.x;
    const int k = threadIdx.x;
    const int lane = k & 31, warp = k >> 5;

    const float d = fmaxf(__expf(dur_out[n * K_ + k]) - 1.0f, 0.0f);
    // warp inclusive scan
    float x = d;
#pragma unroll
    for (int off = 1; off < 32; off <<= 1) {
        float y = __shfl_up_sync(0xFFFFFFFFu, x, off);
        if (lane >= off) x += y;
    }
    if (lane == 31) wsum[warp] = x;
    __syncthreads();
    float off = 0.0f;
#pragma unroll
    for (int w = 0; w < 8; w++) off += (w < warp) ? wsum[w] : 0.0f;
    const float Ev = x + off;
    const float Sv = Ev - d;
    g_SE[(n * K_ + k) * 2 + 0] = Sv;
    g_SE[(n * K_ + k) * 2 + 1] = Ev;
}

// ---------------------------------------------------------------------------
// Kernel 1: Conv1D(3,same)+BN+silu and fold into g/ga. One warp per (n,k).
// Grid 512 blocks x 256 threads (8 warps).
// ---------------------------------------------------------------------------
__global__ __launch_bounds__(256) void conv_fold_kernel(
    const float* __restrict__ V,          // [N,K,M]
    const float* __restrict__ conv_w,     // [3,M,8]
    const float* __restrict__ conv_b,
    const float* __restrict__ bn_gamma, const float* __restrict__ bn_beta,
    const float* __restrict__ bn_mean,  const float* __restrict__ bn_var,
    const float* __restrict__ w1,         // [10,16]
    const float* __restrict__ b1,
    const float* __restrict__ aw1,        // [10,2]
    const float* __restrict__ ab1)
{
    const int tid  = threadIdx.x;
    const int lane = tid & 31;
    const int widx = blockIdx.x * 8 + (tid >> 5);   // 0 .. N*K-1
    const int n = widx >> 8;
    const int k = widx & 255;

    u64 acc2[4] = {0ull, 0ull, 0ull, 0ull};

#pragma unroll
    for (int tap = 0; tap < 3; tap++) {
        const int kk = k - 1 + tap;
        if (kk < 0 || kk >= K_) continue;          // warp-uniform branch
        const float* vrow = V + ((size_t)n * K_ + kk) * M_;
#pragma unroll
        for (int i = 0; i < 3; i++) {
            const int c0 = i * 128 + lane * 4;
            const float4 v = *reinterpret_cast<const float4*>(vrow + c0);
            const float vv[4] = { v.x, v.y, v.z, v.w };
#pragma unroll
            for (int cc = 0; cc < 4; cc++) {
                const u64 vd = pkd(vv[cc]);
                const float4* wp = reinterpret_cast<const float4*>(
                    conv_w + ((size_t)tap * M_ + c0 + cc) * 8);
                const float4 wa = wp[0], wb = wp[1];
                acc2[0] = ffma2(vd, pk2(wa.x, wa.y), acc2[0]);
                acc2[1] = ffma2(vd, pk2(wa.z, wa.w), acc2[1]);
                acc2[2] = ffma2(vd, pk2(wb.x, wb.y), acc2[2]);
                acc2[3] = ffma2(vd, pk2(wb.z, wb.w), acc2[3]);
            }
        }
    }

    float acc[8];
#pragma unroll
    for (int j = 0; j < 4; j++) upk(acc2[j], acc[2 * j], acc[2 * j + 1]);
    // butterfly reduce over 32 lanes -> all lanes get totals
#pragma unroll
    for (int s = 16; s > 0; s >>= 1)
#pragma unroll
        for (int o = 0; o < 8; o++)
            acc[o] += __shfl_xor_sync(0xFFFFFFFFu, acc[o], s);

    // BN + silu
    float cv[8];
#pragma unroll
    for (int o = 0; o < 8; o++) {
        float y = (acc[o] + conv_b[o] - bn_mean[o]) * rsqrtf(bn_var[o] + 1e-3f)
                  * bn_gamma[o] + bn_beta[o];
        cv[o] = siluf(y);
    }

    const float Sv = g_SE[(n * K_ + k) * 2 + 0];
    const float Ev = g_SE[(n * K_ + k) * 2 + 1];

    if (lane < 16) {
        const int j = lane;
        float gj = b1[j] - Sv * w1[j] + Ev * w1[16 + j];
#pragma unroll
        for (int c = 0; c < 8; c++) gj = fmaf(cv[c], w1[(2 + c) * 16 + j], gj);
        g_g[((size_t)n * K_ + k) * 16 + j] = gj;
    } else if (lane < 18) {
        const int p = lane - 16;
        float gp = ab1[p] - Sv * aw1[p] + Ev * aw1[2 + p];
#pragma unroll
        for (int c = 0; c < 8; c++) gp = fmaf(cv[c], aw1[(2 + c) * 2 + p], gp);
        g_ga[((size_t)n * K_ + k) * 2 + p] = gp;
    }
}

// ---------------------------------------------------------------------------
// Kernel 2: score MLP + softmax + aux per (n, t-tile of TT). Block = K_ threads.
// ---------------------------------------------------------------------------
__global__ __launch_bounds__(256) void score_kernel(
    const float* __restrict__ w1,   // [10,16]
    const float* __restrict__ w2,   // [16,16]
    const float* __restrict__ b2,
    const float* __restrict__ w3,   // [16,1]
    const float* __restrict__ b3,
    const float* __restrict__ aw1,  // [10,2]
    const float* __restrict__ aw2,  // [2,2]
    const float* __restrict__ ab2)
{
    __shared__ float2 s_w2p[16][8];   // packed columns of w2: (w2[2j2][i], w2[2j2+1][i])
    __shared__ float s_d1[16], s_w3[16], s_b2[16];
    __shared__ float s_da[2], s_aw2[4], s_ab2[2], s_b3v;
    __shared__ float smax[2][8];
    __shared__ float spart[2][8][4];

    const int k    = threadIdx.x;
    const int lane = k & 31, warp = k >> 5;
    const int n    = blockIdx.y;
    const int tb   = blockIdx.x * TT;

    if (k < 128) {
        const int i = k & 15, j2 = k >> 4;
        s_w2p[i][j2] = make_float2(w2[(2 * j2) * 16 + i], w2[(2 * j2 + 1) * 16 + i]);
    }
    if (k < 16) { s_d1[k] = w1[k] - w1[16 + k]; s_w3[k] = w3[k]; s_b2[k] = b2[k]; }
    if (k < 2)  { s_da[k] = aw1[k] - aw1[2 + k]; s_ab2[k] = ab2[k]; }
    if (k < 4)  { s_aw2[k] = aw2[k]; }
    if (k == 0) { s_b3v = b3[0]; }
    __syncthreads();

    // per-thread folded layer-1 biases (resident across t)
    float g[16];
    {
        const float4* gp = reinterpret_cast<const float4*>(g_g + ((size_t)n * K_ + k) * 16);
#pragma unroll
        for (int q = 0; q < 4; q++) {
            float4 v = gp[q];
            g[4 * q] = v.x; g[4 * q + 1] = v.y; g[4 * q + 2] = v.z; g[4 * q + 3] = v.w;
        }
    }
    const float ga0 = g_ga[((size_t)n * K_ + k) * 2 + 0];
    const float ga1 = g_ga[((size_t)n * K_ + k) * 2 + 1];

    for (int tt = 0; tt < TT; tt++) {
        const int p = tt & 1;
        const float t = (float)(tb + tt + 1);

        // layer 1 (folded) + pack
        u64 h2[8];
#pragma unroll
        for (int j2 = 0; j2 < 8; j2++) {
            float a = siluf(fmaf(t, s_d1[2 * j2],     g[2 * j2]));
            float b = siluf(fmaf(t, s_d1[2 * j2 + 1], g[2 * j2 + 1]));
            h2[j2] = pk2(a, b);
        }
        // layer 2 (packed FFMA2) + output head
        float score = s_b3v;
#pragma unroll
        for (int i = 0; i < 16; i++) {
            u64 acc = pk2(s_b2[i], 0.0f);
            const u64* wrow = reinterpret_cast<const u64*>(&s_w2p[i][0]);
#pragma unroll
            for (int j2 = 0; j2 < 8; j2++) acc = ffma2(h2[j2], wrow[j2], acc);
            float lo, hi; upk(acc, lo, hi);
            score = fmaf(siluf(lo + hi), s_w3[i], score);
        }

        // aux MLP (P=2)
        const float a0 = siluf(fmaf(t, s_da[0], ga0));
        const float a1 = siluf(fmaf(t, s_da[1], ga1));
        const float c20 = siluf(s_ab2[0] + a0 * s_aw2[0] + a1 * s_aw2[2]);
        const float c21 = siluf(s_ab2[1] + a0 * s_aw2[1] + a1 * s_aw2[3]);

        // block max
        float m = score;
#pragma unroll
        for (int s = 16; s > 0; s >>= 1) m = fmaxf(m, __shfl_xor_sync(0xFFFFFFFFu, m, s));
        if (lane == 0) smax[p][warp] = m;
        __syncthreads();
        float mx = smax[p][0];
#pragma unroll
        for (int w = 1; w < 8; w++) mx = fmaxf(mx, smax[p][w]);

        const float e = __expf(score - mx);
        float s0 = e, s1 = e * c20, s2 = e * c21;
#pragma unroll
        for (int s = 16; s > 0; s >>= 1) {
            s0 += __shfl_xor_sync(0xFFFFFFFFu, s0, s);
            s1 += __shfl_xor_sync(0xFFFFFFFFu, s1, s);
            s2 += __shfl_xor_sync(0xFFFFFFFFu, s2, s);
        }
        if (lane == 0) {
            spart[p][warp][0] = s0; spart[p][warp][1] = s1; spart[p][warp][2] = s2;
        }
        __syncthreads();
        float t0s = 0.0f, t1s = 0.0f, t2s = 0.0f;
#pragma unroll
        for (int w = 0; w < 8; w++) {
            t0s += spart[p][w][0]; t1s += spart[p][w][1]; t2s += spart[p][w][2];
        }
        const float inv = __fdividef(1.0f, t0s);

        g_W[((size_t)n * T_ + (tb + tt)) * K_ + k] = e * inv;
        if (k == 0) {
            g_wc[((size_t)n * T_ + (tb + tt)) * 2 + 0] = t1s * inv;
            g_wc[((size_t)n * T_ + (tb + tt)) * 2 + 1] = t2s * inv;
        }
    }
}

// ---------------------------------------------------------------------------
// Kernel 3: O = W @ V + wc @ proj_w.  128x128x16 tiles, 8x8 microtile, FFMA2.
// Grid (M/128, ceil(T/128), N), 256 threads.
// ---------------------------------------------------------------------------
#define GBT 128
#define GBM 128
#define GBK 16

__global__ __launch_bounds__(256) void out_gemm_kernel(
    const float* __restrict__ V,       // [N,K,M]
    const float* __restrict__ proj_w,  // [2,M]
    float* __restrict__ O)             // [N,T,M]
{
    __shared__ __align__(16) float As[GBK][GBT + 4];
    __shared__ __align__(16) float Bs[GBK][GBM];

    const int n  = blockIdx.z;
    const int t0 = blockIdx.y * GBT;
    const int m0 = blockIdx.x * GBM;

    const int tid = threadIdx.x;
    const int tx  = tid & 15;
    const int ty  = tid >> 4;

    const float* A = g_W + (size_t)n * T_ * K_;
    const float* B = V   + (size_t)n * K_ * M_;

    u64 acc2[8][4];
#pragma unroll
    for (int i = 0; i < 8; i++)
#pragma unroll
        for (int j = 0; j < 4; j++) acc2[i][j] = 0ull;

    const int tl = tid >> 1;            // A row within tile
    const int kh = (tid & 1) * 8;       // A k-half
    const int br = tid >> 4;            // B row
    const int bc = (tid & 15) * 8;      // B col

    for (int k0 = 0; k0 < K_; k0 += GBK) {
        // A tile (transpose into k-major smem)
        float4 a0 = make_float4(0.f, 0.f, 0.f, 0.f), a1 = a0;
        const int tg = t0 + tl;
        if (tg < T_) {
            const float* Ap = A + (size_t)tg * K_ + k0 + kh;
            a0 = *reinterpret_cast<const float4*>(Ap);
            a1 = *reinterpret_cast<const float4*>(Ap + 4);
        }
        As[kh + 0][tl] = a0.x; As[kh + 1][tl] = a0.y;
        As[kh + 2][tl] = a0.z; As[kh + 3][tl] = a0.w;
        As[kh + 4][tl] = a1.x; As[kh + 5][tl] = a1.y;
        As[kh + 6][tl] = a1.z; As[kh + 7][tl] = a1.w;
        // B tile (coalesced)
        {
            const float* Bp = B + (size_t)(k0 + br) * M_ + m0 + bc;
            *reinterpret_cast<float4*>(&Bs[br][bc])     = *reinterpret_cast<const float4*>(Bp);
            *reinterpret_cast<float4*>(&Bs[br][bc + 4]) = *reinterpret_cast<const float4*>(Bp + 4);
        }
        __syncthreads();

#pragma unroll
        for (int kk = 0; kk < GBK; kk++) {
            const float4 a40 = *reinterpret_cast<const float4*>(&As[kk][ty * 8]);
            const float4 a41 = *reinterpret_cast<const float4*>(&As[kk][ty * 8 + 4]);
            const float4 b40 = *reinterpret_cast<const float4*>(&Bs[kk][tx * 8]);
            const float4 b41 = *reinterpret_cast<const float4*>(&Bs[kk][tx * 8 + 4]);
            u64 rb2[4] = { pk2(b40.x, b40.y), pk2(b40.z, b40.w),
                           pk2(b41.x, b41.y), pk2(b41.z, b41.w) };
            const float ra[8] = { a40.x, a40.y, a40.z, a40.w,
                                  a41.x, a41.y, a41.z, a41.w };
#pragma unroll
            for (int i = 0; i < 8; i++) {
                const u64 rd = pkd(ra[i]);
#pragma unroll
                for (int j = 0; j < 4; j++)
                    acc2[i][j] = ffma2(rd, rb2[j], acc2[i][j]);
            }
        }
        __syncthreads();
    }

    // epilogue
    float pw0[8], pw1[8];
    {
        const float4* p0 = reinterpret_cast<const float4*>(proj_w + m0 + tx * 8);
        const float4* p1 = reinterpret_cast<const float4*>(proj_w + M_ + m0 + tx * 8);
        float4 v0 = p0[0], v0b = p0[1], v1 = p1[0], v1b = p1[1];
        pw0[0]=v0.x; pw0[1]=v0.y; pw0[2]=v0.z; pw0[3]=v0.w;
        pw0[4]=v0b.x; pw0[5]=v0b.y; pw0[6]=v0b.z; pw0[7]=v0b.w;
        pw1[0]=v1.x; pw1[1]=v1.y; pw1[2]=v1.z; pw1[3]=v1.w;
        pw1[4]=v1b.x; pw1[5]=v1b.y; pw1[6]=v1b.z; pw1[7]=v1b.w;
    }
#pragma unroll
    for (int i = 0; i < 8; i++) {
        const int tg = t0 + ty * 8 + i;
        if (tg >= T_) continue;
        const float wc0 = g_wc[((size_t)n * T_ + tg) * 2 + 0];
        const float wc1 = g_wc[((size_t)n * T_ + tg) * 2 + 1];
        float out[8];
#pragma unroll
        for (int j = 0; j < 4; j++) upk(acc2[i][j], out[2 * j], out[2 * j + 1]);
#pragma unroll
        for (int m = 0; m < 8; m++)
            out[m] = fmaf(wc0, pw0[m], fmaf(wc1, pw1[m], out[m]));
        float* Op = O + ((size_t)n * T_ + tg) * M_ + m0 + tx * 8;
        *reinterpret_cast<float4*>(Op)     = make_float4(out[0], out[1], out[2], out[3]);
        *reinterpret_cast<float4*>(Op + 4) = make_float4(out[4], out[5], out[6], out[7]);
    }
}

// ---------------------------------------------------------------------------
extern "C" void kernel_launch(void* const* d_in, const int* in_sizes, int n_in,
                              void* d_out, int out_size)
{
    const float* V        = (const float*)d_in[0];
    const float* dur      = (const float*)d_in[1];
    const float* conv_w   = (const float*)d_in[2];
    const float* conv_b   = (const float*)d_in[3];
    const float* bn_gamma = (const float*)d_in[4];
    const float* bn_beta  = (const float*)d_in[5];
    const float* bn_mean  = (const float*)d_in[6];
    const float* bn_var   = (const float*)d_in[7];
    const float* w1       = (const float*)d_in[8];
    const float* b1       = (const float*)d_in[9];
    const float* w2       = (const float*)d_in[10];
    const float* b2       = (const float*)d_in[11];
    const float* w3       = (const float*)d_in[12];
    const float* b3       = (const float*)d_in[13];
    const float* aw1      = (const float*)d_in[14];
    const float* ab1      = (const float*)d_in[15];
    const float* aw2      = (const float*)d_in[16];
    const float* ab2      = (const float*)d_in[17];
    const float* proj_w   = (const float*)d_in[18];
    float* O = (float*)d_out;

    scan_kernel<<<N_, K_>>>(dur);
    conv_fold_kernel<<<(N_ * K_) / 8, 256>>>(V, conv_w, conv_b, bn_gamma, bn_beta,
                                             bn_mean, bn_var, w1, b1, aw1, ab1);
    score_kernel<<<dim3(T_ / TT, N_), K_>>>(w1, w2, b2, w3, b3, aw1, aw2, ab2);
    out_gemm_kernel<<<dim3(M_ / GBM, (T_ + GBT - 1) / GBT, N_), 256>>>(V, proj_w, O);
}

// round 3
// speedup vs baseline: 2.1488x; 1.0664x over previous
#include <cuda_runtime.h>
#include <cuda_bf16.h>
#include <cstddef>

#define N_  16
#define K_  256
#define T_  1000
#define M_  384
#define P_  2
#define C8  8
#define TT  8      // t-rows per score block

typedef unsigned long long u64;

// ---------------- scratch (device globals; no allocations) ----------------
__device__ float g_SE[N_ * K_ * 2];    // S, E per (n,k)
__device__ float g_g [N_ * K_ * 16];   // folded layer-1 bias per (n,k)
__device__ float g_ga[N_ * K_ * 2];    // folded aux layer-1 bias per (n,k)
__device__ float g_W [N_ * T_ * K_];   // softmax weights
__device__ float g_wc[N_ * T_ * 2];    // sum_k W*C  (before proj)

// ---------------- packed fp32x2 helpers (sm_100 FFMA2 path) ---------------
__device__ __forceinline__ u64 pk2(float lo, float hi) {
    u64 d; asm("mov.b64 %0, {%1, %2};" : "=l"(d) : "f"(lo), "f"(hi)); return d;
}
__device__ __forceinline__ u64 pkd(float x) {
    u64 d; asm("mov.b64 %0, {%1, %1};" : "=l"(d) : "f"(x)); return d;
}
__device__ __forceinline__ void upk(u64 v, float& lo, float& hi) {
    asm("mov.b64 {%0, %1}, %2;" : "=f"(lo), "=f"(hi) : "l"(v));
}
__device__ __forceinline__ u64 ffma2(u64 a, u64 b, u64 c) {
    u64 d; asm("fma.rn.f32x2 %0, %1, %2, %3;" : "=l"(d) : "l"(a), "l"(b), "l"(c));
    return d;
}

// silu via single-MUFU tanh.approx: x*sigmoid(x) = 0.5x*(1 + tanh(x/2))
__device__ __forceinline__ float siluf(float x) {
    float th;
    const float hx = 0.5f * x;
    asm("tanh.approx.f32 %0, %1;" : "=f"(th) : "f"(hx));
    return fmaf(hx, th, hx);
}

// ---------------------------------------------------------------------------
// Kernel 0: durations + scan -> S,E.  Grid N_, block K_.
// ---------------------------------------------------------------------------
__global__ void scan_kernel(const float* __restrict__ dur_out)
{
    __shared__ float wsum[8];
    const int n = blockIdx.x;
    const int k = threadIdx.x;
    const int lane = k & 31, warp = k >> 5;

    const float d = fmaxf(__expf(dur_out[n * K_ + k]) - 1.0f, 0.0f);
    float x = d;
#pragma unroll
    for (int off = 1; off < 32; off <<= 1) {
        float y = __shfl_up_sync(0xFFFFFFFFu, x, off);
        if (lane >= off) x += y;
    }
    if (lane == 31) wsum[warp] = x;
    __syncthreads();
    float off = 0.0f;
#pragma unroll
    for (int w = 0; w < 8; w++) off += (w < warp) ? wsum[w] : 0.0f;
    const float Ev = x + off;
    const float Sv = Ev - d;
    g_SE[(n * K_ + k) * 2 + 0] = Sv;
    g_SE[(n * K_ + k) * 2 + 1] = Ev;
}

// ---------------------------------------------------------------------------
// Kernel 1: Conv1D(3,same)+BN+silu and fold into g/ga. One warp per (n,k).
// ---------------------------------------------------------------------------
__global__ __launch_bounds__(256) void conv_fold_kernel(
    const float* __restrict__ V,          // [N,K,M]
    const float* __restrict__ conv_w,     // [3,M,8]
    const float* __restrict__ conv_b,
    const float* __restrict__ bn_gamma, const float* __restrict__ bn_beta,
    const float* __restrict__ bn_mean,  const float* __restrict__ bn_var,
    const float* __restrict__ w1,         // [10,16]
    const float* __restrict__ b1,
    const float* __restrict__ aw1,        // [10,2]
    const float* __restrict__ ab1)
{
    const int tid  = threadIdx.x;
    const int lane = tid & 31;
    const int widx = blockIdx.x * 8 + (tid >> 5);   // 0 .. N*K-1
    const int n = widx >> 8;
    const int k = widx & 255;

    u64 acc2[4] = {0ull, 0ull, 0ull, 0ull};

#pragma unroll
    for (int tap = 0; tap < 3; tap++) {
        const int kk = k - 1 + tap;
        if (kk < 0 || kk >= K_) continue;          // warp-uniform branch
        const float* vrow = V + ((size_t)n * K_ + kk) * M_;
#pragma unroll
        for (int i = 0; i < 3; i++) {
            const int c0 = i * 128 + lane * 4;
            const float4 v = *reinterpret_cast<const float4*>(vrow + c0);
            const float vv[4] = { v.x, v.y, v.z, v.w };
#pragma unroll
            for (int cc = 0; cc < 4; cc++) {
                const u64 vd = pkd(vv[cc]);
                const float4* wp = reinterpret_cast<const float4*>(
                    conv_w + ((size_t)tap * M_ + c0 + cc) * 8);
                const float4 wa = wp[0], wb = wp[1];
                acc2[0] = ffma2(vd, pk2(wa.x, wa.y), acc2[0]);
                acc2[1] = ffma2(vd, pk2(wa.z, wa.w), acc2[1]);
                acc2[2] = ffma2(vd, pk2(wb.x, wb.y), acc2[2]);
                acc2[3] = ffma2(vd, pk2(wb.z, wb.w), acc2[3]);
            }
        }
    }

    float acc[8];
#pragma unroll
    for (int j = 0; j < 4; j++) upk(acc2[j], acc[2 * j], acc[2 * j + 1]);
#pragma unroll
    for (int s = 16; s > 0; s >>= 1)
#pragma unroll
        for (int o = 0; o < 8; o++)
            acc[o] += __shfl_xor_sync(0xFFFFFFFFu, acc[o], s);

    float cv[8];
#pragma unroll
    for (int o = 0; o < 8; o++) {
        float y = (acc[o] + conv_b[o] - bn_mean[o]) * rsqrtf(bn_var[o] + 1e-3f)
                  * bn_gamma[o] + bn_beta[o];
        cv[o] = siluf(y);
    }

    const float Sv = g_SE[(n * K_ + k) * 2 + 0];
    const float Ev = g_SE[(n * K_ + k) * 2 + 1];

    if (lane < 16) {
        const int j = lane;
        float gj = b1[j] - Sv * w1[j] + Ev * w1[16 + j];
#pragma unroll
        for (int c = 0; c < 8; c++) gj = fmaf(cv[c], w1[(2 + c) * 16 + j], gj);
        g_g[((size_t)n * K_ + k) * 16 + j] = gj;
    } else if (lane < 18) {
        const int p = lane - 16;
        float gp = ab1[p] - Sv * aw1[p] + Ev * aw1[2 + p];
#pragma unroll
        for (int c = 0; c < 8; c++) gp = fmaf(cv[c], aw1[(2 + c) * 2 + p], gp);
        g_ga[((size_t)n * K_ + k) * 2 + p] = gp;
    }
}

// ---------------------------------------------------------------------------
// Kernel 2: score MLP + softmax + aux per (n, t-tile of TT). Block = K_ threads.
// ---------------------------------------------------------------------------
__global__ __launch_bounds__(256) void score_kernel(
    const float* __restrict__ w1,   // [10,16]
    const float* __restrict__ w2,   // [16,16]
    const float* __restrict__ b2,
    const float* __restrict__ w3,   // [16,1]
    const float* __restrict__ b3,
    const float* __restrict__ aw1,  // [10,2]
    const float* __restrict__ aw2,  // [2,2]
    const float* __restrict__ ab2)
{
    __shared__ float2 s_w2p[16][8];
    __shared__ float s_d1[16], s_w3[16], s_b2[16];
    __shared__ float s_da[2], s_aw2[4], s_ab2[2], s_b3v;
    __shared__ float smax[2][8];
    __shared__ float spart[2][8][4];

    const int k    = threadIdx.x;
    const int lane = k & 31, warp = k >> 5;
    const int n    = blockIdx.y;
    const int tb   = blockIdx.x * TT;

    if (k < 128) {
        const int i = k & 15, j2 = k >> 4;
        s_w2p[i][j2] = make_float2(w2[(2 * j2) * 16 + i], w2[(2 * j2 + 1) * 16 + i]);
    }
    if (k < 16) { s_d1[k] = w1[k] - w1[16 + k]; s_w3[k] = w3[k]; s_b2[k] = b2[k]; }
    if (k < 2)  { s_da[k] = aw1[k] - aw1[2 + k]; s_ab2[k] = ab2[k]; }
    if (k < 4)  { s_aw2[k] = aw2[k]; }
    if (k == 0) { s_b3v = b3[0]; }
    __syncthreads();

    float g[16];
    {
        const float4* gp = reinterpret_cast<const float4*>(g_g + ((size_t)n * K_ + k) * 16);
#pragma unroll
        for (int q = 0; q < 4; q++) {
            float4 v = gp[q];
            g[4 * q] = v.x; g[4 * q + 1] = v.y; g[4 * q + 2] = v.z; g[4 * q + 3] = v.w;
        }
    }
    const float ga0 = g_ga[((size_t)n * K_ + k) * 2 + 0];
    const float ga1 = g_ga[((size_t)n * K_ + k) * 2 + 1];

    for (int tt = 0; tt < TT; tt++) {
        const int p = tt & 1;
        const float t = (float)(tb + tt + 1);

        u64 h2[8];
#pragma unroll
        for (int j2 = 0; j2 < 8; j2++) {
            float a = siluf(fmaf(t, s_d1[2 * j2],     g[2 * j2]));
            float b = siluf(fmaf(t, s_d1[2 * j2 + 1], g[2 * j2 + 1]));
            h2[j2] = pk2(a, b);
        }
        float score = s_b3v;
#pragma unroll
        for (int i = 0; i < 16; i++) {
            u64 acc = pk2(s_b2[i], 0.0f);
            const u64* wrow = reinterpret_cast<const u64*>(&s_w2p[i][0]);
#pragma unroll
            for (int j2 = 0; j2 < 8; j2++) acc = ffma2(h2[j2], wrow[j2], acc);
            float lo, hi; upk(acc, lo, hi);
            score = fmaf(siluf(lo + hi), s_w3[i], score);
        }

        const float a0 = siluf(fmaf(t, s_da[0], ga0));
        const float a1 = siluf(fmaf(t, s_da[1], ga1));
        const float c20 = siluf(s_ab2[0] + a0 * s_aw2[0] + a1 * s_aw2[2]);
        const float c21 = siluf(s_ab2[1] + a0 * s_aw2[1] + a1 * s_aw2[3]);

        float m = score;
#pragma unroll
        for (int s = 16; s > 0; s >>= 1) m = fmaxf(m, __shfl_xor_sync(0xFFFFFFFFu, m, s));
        if (lane == 0) smax[p][warp] = m;
        __syncthreads();
        float mx = smax[p][0];
#pragma unroll
        for (int w = 1; w < 8; w++) mx = fmaxf(mx, smax[p][w]);

        const float e = __expf(score - mx);
        float s0 = e, s1 = e * c20, s2 = e * c21;
#pragma unroll
        for (int s = 16; s > 0; s >>= 1) {
            s0 += __shfl_xor_sync(0xFFFFFFFFu, s0, s);
            s1 += __shfl_xor_sync(0xFFFFFFFFu, s1, s);
            s2 += __shfl_xor_sync(0xFFFFFFFFu, s2, s);
        }
        if (lane == 0) {
            spart[p][warp][0] = s0; spart[p][warp][1] = s1; spart[p][warp][2] = s2;
        }
        __syncthreads();
        float t0s = 0.0f, t1s = 0.0f, t2s = 0.0f;
#pragma unroll
        for (int w = 0; w < 8; w++) {
            t0s += spart[p][w][0]; t1s += spart[p][w][1]; t2s += spart[p][w][2];
        }
        const float inv = __fdividef(1.0f, t0s);

        g_W[((size_t)n * T_ + (tb + tt)) * K_ + k] = e * inv;
        if (k == 0) {
            g_wc[((size_t)n * T_ + (tb + tt)) * 2 + 0] = t1s * inv;
            g_wc[((size_t)n * T_ + (tb + tt)) * 2 + 1] = t2s * inv;
        }
    }
}

// ---------------------------------------------------------------------------
// Kernel 3: O = W @ V + wc @ proj_w.  128x128x16 tiles, 8x8 microtile, FFMA2,
// double-buffered SMEM with register prefetch (1 sync per k-iter).
// ---------------------------------------------------------------------------
#define GBT 128
#define GBM 128
#define GBK 16

__global__ __launch_bounds__(256) void out_gemm_kernel(
    const float* __restrict__ V,       // [N,K,M]
    const float* __restrict__ proj_w,  // [2,M]
    float* __restrict__ O)             // [N,T,M]
{
    __shared__ __align__(16) float As[2][GBK][GBT + 4];
    __shared__ __align__(16) float Bs[2][GBK][GBM];

    const int n  = blockIdx.z;
    const int t0 = blockIdx.y * GBT;
    const int m0 = blockIdx.x * GBM;

    const int tid = threadIdx.x;
    const int tx  = tid & 15;
    const int ty  = tid >> 4;

    const float* A = g_W + (size_t)n * T_ * K_;
    const float* B = V   + (size_t)n * K_ * M_;

    u64 acc2[8][4];
#pragma unroll
    for (int i = 0; i < 8; i++)
#pragma unroll
        for (int j = 0; j < 4; j++) acc2[i][j] = 0ull;

    const int tl = tid >> 1;            // A row within tile (0..127)
    const int kh = (tid & 1) * 8;       // A k-half
    const int br = tid >> 4;            // B row (0..15)
    const int bc = (tid & 15) * 8;      // B col
    const int tg = t0 + tl;
    const bool tok = (tg < T_);
    const float* Abase = A + (size_t)(tok ? tg : 0) * K_ + kh;
    const float* Bbase = B + (size_t)br * M_ + m0 + bc;

    float4 a0, a1, b0, b1;

    // prefetch tile 0
    {
        a0 = make_float4(0.f,0.f,0.f,0.f); a1 = a0;
        if (tok) {
            a0 = *reinterpret_cast<const float4*>(Abase);
            a1 = *reinterpret_cast<const float4*>(Abase + 4);
        }
        b0 = *reinterpret_cast<const float4*>(Bbase);
        b1 = *reinterpret_cast<const float4*>(Bbase + 4);
    }
    // store tile 0 into buf 0
    {
        As[0][kh + 0][tl] = a0.x; As[0][kh + 1][tl] = a0.y;
        As[0][kh + 2][tl] = a0.z; As[0][kh + 3][tl] = a0.w;
        As[0][kh + 4][tl] = a1.x; As[0][kh + 5][tl] = a1.y;
        As[0][kh + 6][tl] = a1.z; As[0][kh + 7][tl] = a1.w;
        *reinterpret_cast<float4*>(&Bs[0][br][bc])     = b0;
        *reinterpret_cast<float4*>(&Bs[0][br][bc + 4]) = b1;
    }
    __syncthreads();

    int buf = 0;
    for (int k0 = 0; k0 < K_; k0 += GBK) {
        const bool more = (k0 + GBK < K_);
        if (more) {
            const float* Ap = Abase + (k0 + GBK);
            const float* Bp = Bbase + (size_t)(k0 + GBK) * M_;
            if (tok) {
                a0 = *reinterpret_cast<const float4*>(Ap);
                a1 = *reinterpret_cast<const float4*>(Ap + 4);
            }
            b0 = *reinterpret_cast<const float4*>(Bp);
            b1 = *reinterpret_cast<const float4*>(Bp + 4);
        }

#pragma unroll
        for (int kk = 0; kk < GBK; kk++) {
            const float4 a40 = *reinterpret_cast<const float4*>(&As[buf][kk][ty * 8]);
            const float4 a41 = *reinterpret_cast<const float4*>(&As[buf][kk][ty * 8 + 4]);
            const float4 b40 = *reinterpret_cast<const float4*>(&Bs[buf][kk][tx * 8]);
            const float4 b41 = *reinterpret_cast<const float4*>(&Bs[buf][kk][tx * 8 + 4]);
            u64 rb2[4] = { pk2(b40.x, b40.y), pk2(b40.z, b40.w),
                           pk2(b41.x, b41.y), pk2(b41.z, b41.w) };
            const float ra[8] = { a40.x, a40.y, a40.z, a40.w,
                                  a41.x, a41.y, a41.z, a41.w };
#pragma unroll
            for (int i = 0; i < 8; i++) {
                const u64 rd = pkd(ra[i]);
#pragma unroll
                for (int j = 0; j < 4; j++)
                    acc2[i][j] = ffma2(rd, rb2[j], acc2[i][j]);
            }
        }

        if (more) {
            const int nb = buf ^ 1;
            As[nb][kh + 0][tl] = a0.x; As[nb][kh + 1][tl] = a0.y;
            As[nb][kh + 2][tl] = a0.z; As[nb][kh + 3][tl] = a0.w;
            As[nb][kh + 4][tl] = a1.x; As[nb][kh + 5][tl] = a1.y;
            As[nb][kh + 6][tl] = a1.z; As[nb][kh + 7][tl] = a1.w;
            *reinterpret_cast<float4*>(&Bs[nb][br][bc])     = b0;
            *reinterpret_cast<float4*>(&Bs[nb][br][bc + 4]) = b1;
            __syncthreads();
        }
        buf ^= 1;
    }

    // epilogue
    float pw0[8], pw1[8];
    {
        const float4* p0 = reinterpret_cast<const float4*>(proj_w + m0 + tx * 8);
        const float4* p1 = reinterpret_cast<const float4*>(proj_w + M_ + m0 + tx * 8);
        float4 v0 = p0[0], v0b = p0[1], v1 = p1[0], v1b = p1[1];
        pw0[0]=v0.x; pw0[1]=v0.y; pw0[2]=v0.z; pw0[3]=v0.w;
        pw0[4]=v0b.x; pw0[5]=v0b.y; pw0[6]=v0b.z; pw0[7]=v0b.w;
        pw1[0]=v1.x; pw1[1]=v1.y; pw1[2]=v1.z; pw1[3]=v1.w;
        pw1[4]=v1b.x; pw1[5]=v1b.y; pw1[6]=v1b.z; pw1[7]=v1b.w;
    }
#pragma unroll
    for (int i = 0; i < 8; i++) {
        const int tr = t0 + ty * 8 + i;
        if (tr >= T_) continue;
        const float wc0 = g_wc[((size_t)n * T_ + tr) * 2 + 0];
        const float wc1 = g_wc[((size_t)n * T_ + tr) * 2 + 1];
        float out[8];
#pragma unroll
        for (int j = 0; j < 4; j++) upk(acc2[i][j], out[2 * j], out[2 * j + 1]);
#pragma unroll
        for (int m = 0; m < 8; m++)
            out[m] = fmaf(wc0, pw0[m], fmaf(wc1, pw1[m], out[m]));
        float* Op = O + ((size_t)n * T_ + tr) * M_ + m0 + tx * 8;
        *reinterpret_cast<float4*>(Op)     = make_float4(out[0], out[1], out[2], out[3]);
        *reinterpret_cast<float4*>(Op + 4) = make_float4(out[4], out[5], out[6], out[7]);
    }
}

// ---------------------------------------------------------------------------
extern "C" void kernel_launch(void* const* d_in, const int* in_sizes, int n_in,
                              void* d_out, int out_size)
{
    const float* V        = (const float*)d_in[0];
    const float* dur      = (const float*)d_in[1];
    const float* conv_w   = (const float*)d_in[2];
    const float* conv_b   = (const float*)d_in[3];
    const float* bn_gamma = (const float*)d_in[4];
    const float* bn_beta  = (const float*)d_in[5];
    const float* bn_mean  = (const float*)d_in[6];
    const float* bn_var   = (const float*)d_in[7];
    const float* w1       = (const float*)d_in[8];
    const float* b1       = (const float*)d_in[9];
    const float* w2       = (const float*)d_in[10];
    const float* b2       = (const float*)d_in[11];
    const float* w3       = (const float*)d_in[12];
    const float* b3       = (const float*)d_in[13];
    const float* aw1      = (const float*)d_in[14];
    const float* ab1      = (const float*)d_in[15];
    const float* aw2      = (const float*)d_in[16];
    const float* ab2      = (const float*)d_in[17];
    const float* proj_w   = (const float*)d_in[18];
    float* O = (float*)d_out;

    scan_kernel<<<N_, K_>>>(dur);
    conv_fold_kernel<<<(N_ * K_) / 8, 256>>>(V, conv_w, conv_b, bn_gamma, bn_beta,
                                             bn_mean, bn_var, w1, b1, aw1, ab1);
    score_kernel<<<dim3(T_ / TT, N_), K_>>>(w1, w2, b2, w3, b3, aw1, aw2, ab2);
    out_gemm_kernel<<<dim3(M_ / GBM, (T_ + GBT - 1) / GBT, N_), 256>>>(V, proj_w, O);
}